// round 1
// baseline (speedup 1.0000x reference)
#include <cuda_runtime.h>
#include <math.h>

#define NN 50000
#define EE 800000

// ---------------- scratch (allocation-free: __device__ globals) ----------------
__device__ float g_qkv[NN * 384];   // [node][ q(128) | k(128) | v(128) ]
__device__ float g_sc [EE * 8];     // per-(edge,head) score, then exp value
__device__ float g_m  [NN * 8];     // segment max
__device__ float g_den[NN * 8];     // segment sum of exp
__device__ float g_agg[NN * 128];   // aggregated attention output
__device__ float g_tmp[NN * 128];   // after Wo, before LN

// ---------------- init ----------------
__global__ void init_k() {
    int tid = blockIdx.x * blockDim.x + threadIdx.x;
    int stride = gridDim.x * blockDim.x;
    for (int i = tid; i < NN * 8; i += stride) {
        g_m[i]   = __int_as_float(0xFF800000);  // -inf
        g_den[i] = 0.f;
    }
    for (int i = tid; i < NN * 128; i += stride) g_agg[i] = 0.f;
}

// ---------------- generic [N,128]x[128,128] SGEMM + bias ----------------
// BM=128, BN=128, BK=8, 256 threads, 8x8 per-thread micro-tile.
__global__ __launch_bounds__(256) void gemm_128(
    const float* __restrict__ A, const float* __restrict__ W,
    const float* __restrict__ bias, float* __restrict__ C,
    int ldc, int coloff)
{
    __shared__ float As[8][128];
    __shared__ float Bs[8][128];

    const int rowBase = blockIdx.x * 128;
    const int t  = threadIdx.x;
    const int ty = t >> 4;       // 0..15
    const int tx = t & 15;       // 0..15

    float acc[8][8];
#pragma unroll
    for (int i = 0; i < 8; i++)
#pragma unroll
        for (int j = 0; j < 8; j++) acc[i][j] = 0.f;

    const int ar = t >> 1;           // 0..127
    const int ac = (t & 1) << 2;     // 0 or 4
    const int br = t >> 5;           // 0..7
    const int bc = (t & 31) << 2;    // 0..124
    const int grow = rowBase + ar;
    const bool rok = grow < NN;
    const float* aptr = A + (size_t)grow * 128 + ac;

    for (int k0 = 0; k0 < 128; k0 += 8) {
        float4 av = make_float4(0.f, 0.f, 0.f, 0.f);
        if (rok) av = *reinterpret_cast<const float4*>(aptr + k0);
        As[ac + 0][ar] = av.x; As[ac + 1][ar] = av.y;
        As[ac + 2][ar] = av.z; As[ac + 3][ar] = av.w;
        *reinterpret_cast<float4*>(&Bs[br][bc]) =
            *reinterpret_cast<const float4*>(W + (size_t)(k0 + br) * 128 + bc);
        __syncthreads();

#pragma unroll
        for (int k = 0; k < 8; k++) {
            float4 a0 = *reinterpret_cast<const float4*>(&As[k][ty * 8]);
            float4 a1 = *reinterpret_cast<const float4*>(&As[k][ty * 8 + 4]);
            float4 b0 = *reinterpret_cast<const float4*>(&Bs[k][tx * 8]);
            float4 b1 = *reinterpret_cast<const float4*>(&Bs[k][tx * 8 + 4]);
            float ra[8] = {a0.x, a0.y, a0.z, a0.w, a1.x, a1.y, a1.z, a1.w};
            float rb[8] = {b0.x, b0.y, b0.z, b0.w, b1.x, b1.y, b1.z, b1.w};
#pragma unroll
            for (int i = 0; i < 8; i++)
#pragma unroll
                for (int j = 0; j < 8; j++)
                    acc[i][j] = fmaf(ra[i], rb[j], acc[i][j]);
        }
        __syncthreads();
    }

    float bb[8];
#pragma unroll
    for (int j = 0; j < 8; j++) bb[j] = bias[tx * 8 + j];

#pragma unroll
    for (int i = 0; i < 8; i++) {
        int row = rowBase + ty * 8 + i;
        if (row < NN) {
            float* cp = C + (size_t)row * ldc + coloff + tx * 8;
            float4 o0 = make_float4(acc[i][0] + bb[0], acc[i][1] + bb[1],
                                    acc[i][2] + bb[2], acc[i][3] + bb[3]);
            float4 o1 = make_float4(acc[i][4] + bb[4], acc[i][5] + bb[5],
                                    acc[i][6] + bb[6], acc[i][7] + bb[7]);
            *reinterpret_cast<float4*>(cp)     = o0;
            *reinterpret_cast<float4*>(cp + 4) = o1;
        }
    }
}

// ---------------- per-(edge,head) scores + atomic segment max ----------------
__global__ __launch_bounds__(256) void score_k(
    const int* __restrict__ ei, const float* __restrict__ ea,
    const float* __restrict__ We, const float* __restrict__ be)
{
    __shared__ float sWe[256];
    __shared__ float sbe[8];
    int t = threadIdx.x;
    sWe[t] = We[t];
    if (t < 8) sbe[t] = be[t];
    __syncthreads();

    int gid = blockIdx.x * 256 + t;
    if (gid >= EE * 8) return;
    int e = gid >> 3, h = gid & 7;
    int src = ei[e], dst = ei[EE + e];

    const float4* qp = reinterpret_cast<const float4*>(&g_qkv[(size_t)dst * 384 + h * 16]);
    const float4* kp = reinterpret_cast<const float4*>(&g_qkv[(size_t)src * 384 + 128 + h * 16]);
    float dot = 0.f;
#pragma unroll
    for (int i = 0; i < 4; i++) {
        float4 a = qp[i], b = kp[i];
        dot += a.x * b.x + a.y * b.y + a.z * b.z + a.w * b.w;
    }

    float s = sbe[h];
    const float4* ep = reinterpret_cast<const float4*>(ea + (size_t)e * 32);
#pragma unroll
    for (int i = 0; i < 8; i++) {
        float4 v = ep[i];
        s += v.x * sWe[(i * 4 + 0) * 8 + h] + v.y * sWe[(i * 4 + 1) * 8 + h]
           + v.z * sWe[(i * 4 + 2) * 8 + h] + v.w * sWe[(i * 4 + 3) * 8 + h];
    }
    s += dot * 0.25f;  // DH^-0.5 = 1/4
    g_sc[gid] = s;

    // float atomic-max via signed-max / unsigned-min split (order independent)
    float* maddr = &g_m[dst * 8 + h];
    int iv = __float_as_int(s);
    if (iv >= 0) atomicMax((int*)maddr, iv);
    else         atomicMin((unsigned int*)maddr, (unsigned int)iv);
}

// ---------------- exp(s - m) + atomic segment sum ----------------
__global__ __launch_bounds__(256) void exp_k(const int* __restrict__ ei)
{
    int gid = blockIdx.x * 256 + threadIdx.x;
    if (gid >= EE * 8) return;
    int e = gid >> 3, h = gid & 7;
    int dst = ei[EE + e];
    float m = g_m[dst * 8 + h];
    float ex = expf(g_sc[gid] - m);
    g_sc[gid] = ex;
    atomicAdd(&g_den[dst * 8 + h], ex);
}

// ---------------- weighted aggregate (scatter-add) ----------------
__global__ __launch_bounds__(256) void agg_k(const int* __restrict__ ei)
{
    int gid = blockIdx.x * 256 + threadIdx.x;
    if (gid >= EE * 8) return;
    int e = gid >> 3, h = gid & 7;
    int src = ei[e], dst = ei[EE + e];
    float alpha = g_sc[gid] / g_den[dst * 8 + h];
    const float4* vp = reinterpret_cast<const float4*>(&g_qkv[(size_t)src * 384 + 256 + h * 16]);
    float* op = &g_agg[dst * 128 + h * 16];
#pragma unroll
    for (int i = 0; i < 4; i++) {
        float4 v = vp[i];
        atomicAdd(op + i * 4 + 0, v.x * alpha);
        atomicAdd(op + i * 4 + 1, v.y * alpha);
        atomicAdd(op + i * 4 + 2, v.z * alpha);
        atomicAdd(op + i * 4 + 3, v.w * alpha);
    }
}

// ---------------- LayerNorm ----------------
__global__ __launch_bounds__(128) void ln_k(
    const float* __restrict__ in, const float* __restrict__ gamma,
    const float* __restrict__ beta, float* __restrict__ out)
{
    int node = blockIdx.x;
    int t = threadIdx.x;
    float v = in[node * 128 + t];

    float s = v;
#pragma unroll
    for (int o = 16; o > 0; o >>= 1) s += __shfl_xor_sync(0xffffffffu, s, o);
    __shared__ float sh[4], sh2[4];
    int w = t >> 5, l = t & 31;
    if (l == 0) sh[w] = s;
    __syncthreads();
    float mean = (sh[0] + sh[1] + sh[2] + sh[3]) * (1.0f / 128.0f);

    float d = v - mean;
    float s2 = d * d;
#pragma unroll
    for (int o = 16; o > 0; o >>= 1) s2 += __shfl_xor_sync(0xffffffffu, s2, o);
    if (l == 0) sh2[w] = s2;
    __syncthreads();
    float var = (sh2[0] + sh2[1] + sh2[2] + sh2[3]) * (1.0f / 128.0f);

    out[node * 128 + t] = d * rsqrtf(var + 1e-5f) * gamma[t] + beta[t];
}

// ---------------- launch ----------------
extern "C" void kernel_launch(void* const* d_in, const int* in_sizes, int n_in,
                              void* d_out, int out_size)
{
    const float* x     = (const float*)d_in[0];
    const float* ea    = (const float*)d_in[1];
    const float* Wq    = (const float*)d_in[2];
    const float* bq    = (const float*)d_in[3];
    const float* Wk    = (const float*)d_in[4];
    const float* bk    = (const float*)d_in[5];
    const float* Wv    = (const float*)d_in[6];
    const float* bv    = (const float*)d_in[7];
    const float* We    = (const float*)d_in[8];
    const float* be    = (const float*)d_in[9];
    const float* Wo    = (const float*)d_in[10];
    const float* bo    = (const float*)d_in[11];
    const float* gamma = (const float*)d_in[12];
    const float* beta  = (const float*)d_in[13];
    const int*   ei    = (const int*)d_in[14];
    float* out = (float*)d_out;

    float *qkv, *agg, *tmp;
    cudaGetSymbolAddress((void**)&qkv, g_qkv);
    cudaGetSymbolAddress((void**)&agg, g_agg);
    cudaGetSymbolAddress((void**)&tmp, g_tmp);

    const int nTiles = (NN + 127) / 128;   // 391
    const int gridE  = (EE * 8 + 255) / 256;

    init_k<<<2048, 256>>>();
    gemm_128<<<nTiles, 256>>>(x, Wq, bq, qkv, 384, 0);
    gemm_128<<<nTiles, 256>>>(x, Wk, bk, qkv, 384, 128);
    gemm_128<<<nTiles, 256>>>(x, Wv, bv, qkv, 384, 256);
    score_k<<<gridE, 256>>>(ei, ea, We, be);
    exp_k<<<gridE, 256>>>(ei);
    agg_k<<<gridE, 256>>>(ei);
    gemm_128<<<nTiles, 256>>>(agg, Wo, bo, tmp, 128, 0);
    ln_k<<<NN, 128>>>(tmp, gamma, beta, out);
}

// round 2
// speedup vs baseline: 1.5495x; 1.5495x over previous
#include <cuda_runtime.h>
#include <math.h>

#define NN 50000
#define EE 800000

// ---------------- scratch (allocation-free: __device__ globals) ----------------
__device__ float g_qkv[NN * 384];     // [node][ q(128) | k(128) | v(128) ]
__device__ float g_agg[NN * 128];     // aggregated attention output
__device__ float g_tmp[NN * 128];     // after Wo, before LN
__device__ int   g_cnt[NN];           // per-dst degree / scatter cursor
__device__ int   g_off[NN + 1];       // CSR offsets
__device__ int   g_list[EE];          // edge ids grouped by dst

// ---------------- CSR build ----------------
__global__ void zero_cnt_k() {
    int i = blockIdx.x * blockDim.x + threadIdx.x;
    if (i < NN) g_cnt[i] = 0;
}

__global__ void hist_k(const int* __restrict__ ei) {
    int e = blockIdx.x * blockDim.x + threadIdx.x;
    if (e < EE) atomicAdd(&g_cnt[ei[EE + e]], 1);
}

// single-block exclusive scan over 50000 counts; also resets cnt to 0
__global__ __launch_bounds__(1024) void scan_k() {
    __shared__ float dummy;  (void)dummy;
    __shared__ int ssum[1024];
    const int T = 1024;
    const int CH = (NN + T - 1) / T;   // 49
    int t = threadIdx.x;
    int base = t * CH;

    int loc = 0;
    for (int i = 0; i < CH; i++) {
        int idx = base + i;
        if (idx < NN) loc += g_cnt[idx];
    }
    ssum[t] = loc;
    __syncthreads();
    // Hillis-Steele inclusive scan
    for (int o = 1; o < T; o <<= 1) {
        int v = (t >= o) ? ssum[t - o] : 0;
        __syncthreads();
        ssum[t] += v;
        __syncthreads();
    }
    int run = (t == 0) ? 0 : ssum[t - 1];   // exclusive prefix of chunk
    for (int i = 0; i < CH; i++) {
        int idx = base + i;
        if (idx < NN) {
            int c = g_cnt[idx];
            g_off[idx] = run;
            g_cnt[idx] = 0;
            run += c;
        }
    }
    if (t == T - 1) g_off[NN] = run;
}

__global__ void scatter_k(const int* __restrict__ ei) {
    int e = blockIdx.x * blockDim.x + threadIdx.x;
    if (e < EE) {
        int dst = ei[EE + e];
        int pos = atomicAdd(&g_cnt[dst], 1);
        g_list[g_off[dst] + pos] = e;
    }
}

// ---------------- generic [N,128]x[128,128] SGEMM + bias ----------------
__global__ __launch_bounds__(256) void gemm_128(
    const float* __restrict__ A, const float* __restrict__ W,
    const float* __restrict__ bias, float* __restrict__ C,
    int ldc, int coloff)
{
    __shared__ float As[8][128];
    __shared__ float Bs[8][128];

    const int rowBase = blockIdx.x * 128;
    const int t  = threadIdx.x;
    const int ty = t >> 4;
    const int tx = t & 15;

    float acc[8][8];
#pragma unroll
    for (int i = 0; i < 8; i++)
#pragma unroll
        for (int j = 0; j < 8; j++) acc[i][j] = 0.f;

    const int ar = t >> 1;
    const int ac = (t & 1) << 2;
    const int br = t >> 5;
    const int bc = (t & 31) << 2;
    const int grow = rowBase + ar;
    const bool rok = grow < NN;
    const float* aptr = A + (size_t)grow * 128 + ac;

    for (int k0 = 0; k0 < 128; k0 += 8) {
        float4 av = make_float4(0.f, 0.f, 0.f, 0.f);
        if (rok) av = *reinterpret_cast<const float4*>(aptr + k0);
        As[ac + 0][ar] = av.x; As[ac + 1][ar] = av.y;
        As[ac + 2][ar] = av.z; As[ac + 3][ar] = av.w;
        *reinterpret_cast<float4*>(&Bs[br][bc]) =
            *reinterpret_cast<const float4*>(W + (size_t)(k0 + br) * 128 + bc);
        __syncthreads();

#pragma unroll
        for (int k = 0; k < 8; k++) {
            float4 a0 = *reinterpret_cast<const float4*>(&As[k][ty * 8]);
            float4 a1 = *reinterpret_cast<const float4*>(&As[k][ty * 8 + 4]);
            float4 b0 = *reinterpret_cast<const float4*>(&Bs[k][tx * 8]);
            float4 b1 = *reinterpret_cast<const float4*>(&Bs[k][tx * 8 + 4]);
            float ra[8] = {a0.x, a0.y, a0.z, a0.w, a1.x, a1.y, a1.z, a1.w};
            float rb[8] = {b0.x, b0.y, b0.z, b0.w, b1.x, b1.y, b1.z, b1.w};
#pragma unroll
            for (int i = 0; i < 8; i++)
#pragma unroll
                for (int j = 0; j < 8; j++)
                    acc[i][j] = fmaf(ra[i], rb[j], acc[i][j]);
        }
        __syncthreads();
    }

    float bb[8];
#pragma unroll
    for (int j = 0; j < 8; j++) bb[j] = bias[tx * 8 + j];

#pragma unroll
    for (int i = 0; i < 8; i++) {
        int row = rowBase + ty * 8 + i;
        if (row < NN) {
            float* cp = C + (size_t)row * ldc + coloff + tx * 8;
            float4 o0 = make_float4(acc[i][0] + bb[0], acc[i][1] + bb[1],
                                    acc[i][2] + bb[2], acc[i][3] + bb[3]);
            float4 o1 = make_float4(acc[i][4] + bb[4], acc[i][5] + bb[5],
                                    acc[i][6] + bb[6], acc[i][7] + bb[7]);
            *reinterpret_cast<float4*>(cp)     = o0;
            *reinterpret_cast<float4*>(cp + 4) = o1;
        }
    }
}

// ---------------- fused attention: warp per dst node, online softmax ----------------
// lane l: head g = l>>2, sub j = l&3. Each lane owns 4 consecutive channels (l*4..l*4+3).
__global__ __launch_bounds__(256) void attn_k(
    const int* __restrict__ ei, const float* __restrict__ ea,
    const float* __restrict__ We, const float* __restrict__ be)
{
    __shared__ float sWe[256];   // [32][8]
    __shared__ float sbe[8];
    {
        int t = threadIdx.x;
        if (t < 256) sWe[t] = We[t];
        if (t < 8) sbe[t] = be[t];
    }
    __syncthreads();

    const int warp = threadIdx.x >> 5;
    const int lane = threadIdx.x & 31;
    const int node = blockIdx.x * 8 + warp;
    if (node >= NN) return;

    const int g = lane >> 2;
    const int j = lane & 3;

    const int beg = g_off[node];
    const int end = g_off[node + 1];

    float* op = &g_agg[(size_t)node * 128 + lane * 4];
    if (beg == end) {
        *reinterpret_cast<float4*>(op) = make_float4(0.f, 0.f, 0.f, 0.f);
        return;
    }

    // q for this lane's 4 channels
    float4 qv = *reinterpret_cast<const float4*>(&g_qkv[(size_t)node * 384 + lane * 4]);
    const float beh = sbe[g];

    float m = -__int_as_float(0x7F800000);  // -inf
    float d = 0.f;
    float4 acc = make_float4(0.f, 0.f, 0.f, 0.f);

    for (int idx = beg; idx < end; idx++) {
        int e = g_list[idx];
        int src = ei[e];
        const float* kb = &g_qkv[(size_t)src * 384 + 128];

        float4 kv = *reinterpret_cast<const float4*>(kb + lane * 4);
        float dot = qv.x * kv.x + qv.y * kv.y + qv.z * kv.z + qv.w * kv.w;
        dot += __shfl_xor_sync(0xffffffffu, dot, 1);
        dot += __shfl_xor_sync(0xffffffffu, dot, 2);

        // edge-attr term: lane j handles ea[e][8j..8j+8)
        const float4* ep = reinterpret_cast<const float4*>(ea + (size_t)e * 32 + j * 8);
        float4 e0 = ep[0], e1 = ep[1];
        const float* wr = &sWe[(j * 8) * 8 + g];
        float part = e0.x * wr[0]  + e0.y * wr[8]  + e0.z * wr[16] + e0.w * wr[24]
                   + e1.x * wr[32] + e1.y * wr[40] + e1.z * wr[48] + e1.w * wr[56];
        part += __shfl_xor_sync(0xffffffffu, part, 1);
        part += __shfl_xor_sync(0xffffffffu, part, 2);

        float s = dot * 0.25f + part + beh;

        float mn = fmaxf(m, s);
        float scale = __expf(m - mn);   // m=-inf first iter -> 0
        float p = __expf(s - mn);
        d = d * scale + p;

        float4 vv = *reinterpret_cast<const float4*>(&g_qkv[(size_t)src * 384 + 256 + lane * 4]);
        acc.x = acc.x * scale + p * vv.x;
        acc.y = acc.y * scale + p * vv.y;
        acc.z = acc.z * scale + p * vv.z;
        acc.w = acc.w * scale + p * vv.w;
        m = mn;
    }

    float inv = 1.0f / d;
    *reinterpret_cast<float4*>(op) =
        make_float4(acc.x * inv, acc.y * inv, acc.z * inv, acc.w * inv);
}

// ---------------- LayerNorm ----------------
__global__ __launch_bounds__(128) void ln_k(
    const float* __restrict__ in, const float* __restrict__ gamma,
    const float* __restrict__ beta, float* __restrict__ out)
{
    int node = blockIdx.x;
    int t = threadIdx.x;
    float v = in[node * 128 + t];

    float s = v;
#pragma unroll
    for (int o = 16; o > 0; o >>= 1) s += __shfl_xor_sync(0xffffffffu, s, o);
    __shared__ float sh[4], sh2[4];
    int w = t >> 5, l = t & 31;
    if (l == 0) sh[w] = s;
    __syncthreads();
    float mean = (sh[0] + sh[1] + sh[2] + sh[3]) * (1.0f / 128.0f);

    float dv = v - mean;
    float s2 = dv * dv;
#pragma unroll
    for (int o = 16; o > 0; o >>= 1) s2 += __shfl_xor_sync(0xffffffffu, s2, o);
    if (l == 0) sh2[w] = s2;
    __syncthreads();
    float var = (sh2[0] + sh2[1] + sh2[2] + sh2[3]) * (1.0f / 128.0f);

    out[node * 128 + t] = dv * rsqrtf(var + 1e-5f) * gamma[t] + beta[t];
}

// ---------------- launch ----------------
extern "C" void kernel_launch(void* const* d_in, const int* in_sizes, int n_in,
                              void* d_out, int out_size)
{
    const float* x     = (const float*)d_in[0];
    const float* ea    = (const float*)d_in[1];
    const float* Wq    = (const float*)d_in[2];
    const float* bq    = (const float*)d_in[3];
    const float* Wk    = (const float*)d_in[4];
    const float* bk    = (const float*)d_in[5];
    const float* Wv    = (const float*)d_in[6];
    const float* bv    = (const float*)d_in[7];
    const float* We    = (const float*)d_in[8];
    const float* be    = (const float*)d_in[9];
    const float* Wo    = (const float*)d_in[10];
    const float* bo    = (const float*)d_in[11];
    const float* gamma = (const float*)d_in[12];
    const float* beta  = (const float*)d_in[13];
    const int*   ei    = (const int*)d_in[14];
    float* out = (float*)d_out;

    float *qkv, *agg, *tmp;
    cudaGetSymbolAddress((void**)&qkv, g_qkv);
    cudaGetSymbolAddress((void**)&agg, g_agg);
    cudaGetSymbolAddress((void**)&tmp, g_tmp);

    const int nTiles = (NN + 127) / 128;   // 391

    // CSR build (overlaps conceptually with QKV GEMMs on the same stream)
    zero_cnt_k<<<(NN + 255) / 256, 256>>>();
    hist_k<<<(EE + 255) / 256, 256>>>(ei);
    scan_k<<<1, 1024>>>();
    scatter_k<<<(EE + 255) / 256, 256>>>(ei);

    gemm_128<<<nTiles, 256>>>(x, Wq, bq, qkv, 384, 0);
    gemm_128<<<nTiles, 256>>>(x, Wk, bk, qkv, 384, 128);
    gemm_128<<<nTiles, 256>>>(x, Wv, bv, qkv, 384, 256);

    attn_k<<<(NN + 7) / 8, 256>>>(ei, ea, We, be);

    gemm_128<<<nTiles, 256>>>(agg, Wo, bo, tmp, 128, 0);
    ln_k<<<NN, 128>>>(tmp, gamma, beta, out);
}

// round 3
// speedup vs baseline: 2.6131x; 1.6864x over previous
#include <cuda_runtime.h>
#include <math.h>

#define NN 50000
#define EE 800000

// ---------------- scratch ----------------
__device__ float g_qkv[NN * 384];     // [node][ q | k | v ]
__device__ float g_agg[NN * 128];
__device__ float g_tmp[NN * 128];
__device__ int   g_cnt[NN];
__device__ int   g_off[NN + 1];
__device__ int   g_list[EE];

// ---------------- CSR build ----------------
__global__ void zero_cnt_k() {
    int i = blockIdx.x * blockDim.x + threadIdx.x;
    if (i < NN) g_cnt[i] = 0;
}

__global__ void hist_k(const int* __restrict__ ei) {
    int e = blockIdx.x * blockDim.x + threadIdx.x;
    if (e < EE) atomicAdd(&g_cnt[ei[EE + e]], 1);
}

__global__ __launch_bounds__(1024) void scan_k() {
    __shared__ int ssum[1024];
    const int T = 1024;
    const int CH = (NN + T - 1) / T;
    int t = threadIdx.x;
    int base = t * CH;

    int loc = 0;
    for (int i = 0; i < CH; i++) {
        int idx = base + i;
        if (idx < NN) loc += g_cnt[idx];
    }
    ssum[t] = loc;
    __syncthreads();
    for (int o = 1; o < T; o <<= 1) {
        int v = (t >= o) ? ssum[t - o] : 0;
        __syncthreads();
        ssum[t] += v;
        __syncthreads();
    }
    int run = (t == 0) ? 0 : ssum[t - 1];
    for (int i = 0; i < CH; i++) {
        int idx = base + i;
        if (idx < NN) {
            int c = g_cnt[idx];
            g_off[idx] = run;
            g_cnt[idx] = 0;
            run += c;
        }
    }
    if (t == T - 1) g_off[NN] = run;
}

__global__ void scatter_k(const int* __restrict__ ei) {
    int e = blockIdx.x * blockDim.x + threadIdx.x;
    if (e < EE) {
        int dst = ei[EE + e];
        int pos = atomicAdd(&g_cnt[dst], 1);
        g_list[g_off[dst] + pos] = e;
    }
}

// ---------------- TF32 tensor-core GEMM: [N,128]x[128,128]+bias ----------------
__device__ __forceinline__ unsigned f2tf32(float f) {
    unsigned u;
    asm("cvt.rna.tf32.f32 %0, %1;" : "=r"(u) : "f"(f));
    return u;
}

__device__ __forceinline__ void mma_tf32(
    float& c0, float& c1, float& c2, float& c3,
    unsigned a0, unsigned a1, unsigned a2, unsigned a3,
    unsigned b0, unsigned b1)
{
    asm volatile(
        "mma.sync.aligned.m16n8k8.row.col.f32.tf32.tf32.f32 "
        "{%0,%1,%2,%3}, {%4,%5,%6,%7}, {%8,%9}, {%0,%1,%2,%3};"
        : "+f"(c0), "+f"(c1), "+f"(c2), "+f"(c3)
        : "r"(a0), "r"(a1), "r"(a2), "r"(a3), "r"(b0), "r"(b1));
}

#define BK 16
__global__ __launch_bounds__(256) void gemm_tf32(
    const float* __restrict__ A, const float* __restrict__ W,
    const float* __restrict__ bias, float* __restrict__ C,
    int ldc, int coloff)
{
    __shared__ unsigned As[2][BK][136];   // [k][m], padded
    __shared__ unsigned Bs[2][BK][128];   // [k][n]

    const int t    = threadIdx.x;
    const int wid  = t >> 5;
    const int lane = t & 31;
    const int wm   = wid & 1;          // 0..1  (m 64-blocks)
    const int wn   = wid >> 1;         // 0..3  (n 32-blocks)
    const int tig  = lane & 3;
    const int grp  = lane >> 2;
    const int rowBase = blockIdx.x * 128;

    float acc[4][4][4];
#pragma unroll
    for (int mi = 0; mi < 4; mi++)
#pragma unroll
        for (int ni = 0; ni < 4; ni++)
#pragma unroll
            for (int r = 0; r < 4; r++) acc[mi][ni][r] = 0.f;

    // A tile: 128x16 = 512 float4; thread handles id=t, t+256
    const int aRow0 = t >> 2;                 // ids t:     row, col4
    const int aC0   = (t & 3) << 2;
    const int aRow1 = (t + 256) >> 2;
    const int aC1   = aC0;                    // (t+256)&3 == t&3
    // B tile: 16x128 = 512 float4
    const int bK0 = t >> 5;
    const int bN0 = (t & 31) << 2;
    const int bK1 = bK0 + 8;
    const int bN1 = bN0;

    const bool aOk0 = rowBase + aRow0 < NN;
    const bool aOk1 = rowBase + aRow1 < NN;
    const float* aP0 = A + (size_t)(rowBase + aRow0) * 128 + aC0;
    const float* aP1 = A + (size_t)(rowBase + aRow1) * 128 + aC1;

    float4 fa0 = make_float4(0.f,0.f,0.f,0.f), fa1 = fa0, fb0, fb1;
    // preload k0=0
    if (aOk0) fa0 = *reinterpret_cast<const float4*>(aP0);
    if (aOk1) fa1 = *reinterpret_cast<const float4*>(aP1);
    fb0 = *reinterpret_cast<const float4*>(W + (size_t)bK0 * 128 + bN0);
    fb1 = *reinterpret_cast<const float4*>(W + (size_t)bK1 * 128 + bN1);

    int buf = 0;
    {
        As[0][aC0+0][aRow0] = f2tf32(fa0.x); As[0][aC0+1][aRow0] = f2tf32(fa0.y);
        As[0][aC0+2][aRow0] = f2tf32(fa0.z); As[0][aC0+3][aRow0] = f2tf32(fa0.w);
        As[0][aC1+0][aRow1] = f2tf32(fa1.x); As[0][aC1+1][aRow1] = f2tf32(fa1.y);
        As[0][aC1+2][aRow1] = f2tf32(fa1.z); As[0][aC1+3][aRow1] = f2tf32(fa1.w);
        Bs[0][bK0][bN0+0] = f2tf32(fb0.x); Bs[0][bK0][bN0+1] = f2tf32(fb0.y);
        Bs[0][bK0][bN0+2] = f2tf32(fb0.z); Bs[0][bK0][bN0+3] = f2tf32(fb0.w);
        Bs[0][bK1][bN1+0] = f2tf32(fb1.x); Bs[0][bK1][bN1+1] = f2tf32(fb1.y);
        Bs[0][bK1][bN1+2] = f2tf32(fb1.z); Bs[0][bK1][bN1+3] = f2tf32(fb1.w);
    }
    __syncthreads();

    for (int kb = 0; kb < 8; kb++) {
        const int nk = (kb + 1) * BK;
        if (kb < 7) {
            fa0 = make_float4(0.f,0.f,0.f,0.f); fa1 = fa0;
            if (aOk0) fa0 = *reinterpret_cast<const float4*>(aP0 + nk);
            if (aOk1) fa1 = *reinterpret_cast<const float4*>(aP1 + nk);
            fb0 = *reinterpret_cast<const float4*>(W + (size_t)(nk + bK0) * 128 + bN0);
            fb1 = *reinterpret_cast<const float4*>(W + (size_t)(nk + bK1) * 128 + bN1);
        }

#pragma unroll
        for (int ks = 0; ks < 2; ks++) {
            const int k0 = ks * 8;
            unsigned a[4][4];
#pragma unroll
            for (int mi = 0; mi < 4; mi++) {
                int mr = wm * 64 + mi * 16 + grp;
                a[mi][0] = As[buf][k0 + tig][mr];
                a[mi][1] = As[buf][k0 + tig][mr + 8];
                a[mi][2] = As[buf][k0 + tig + 4][mr];
                a[mi][3] = As[buf][k0 + tig + 4][mr + 8];
            }
            unsigned b[4][2];
#pragma unroll
            for (int ni = 0; ni < 4; ni++) {
                int nc = wn * 32 + ni * 8 + grp;
                b[ni][0] = Bs[buf][k0 + tig][nc];
                b[ni][1] = Bs[buf][k0 + tig + 4][nc];
            }
#pragma unroll
            for (int mi = 0; mi < 4; mi++)
#pragma unroll
                for (int ni = 0; ni < 4; ni++)
                    mma_tf32(acc[mi][ni][0], acc[mi][ni][1], acc[mi][ni][2], acc[mi][ni][3],
                             a[mi][0], a[mi][1], a[mi][2], a[mi][3],
                             b[ni][0], b[ni][1]);
        }

        if (kb < 7) {
            int nb = buf ^ 1;
            As[nb][aC0+0][aRow0] = f2tf32(fa0.x); As[nb][aC0+1][aRow0] = f2tf32(fa0.y);
            As[nb][aC0+2][aRow0] = f2tf32(fa0.z); As[nb][aC0+3][aRow0] = f2tf32(fa0.w);
            As[nb][aC1+0][aRow1] = f2tf32(fa1.x); As[nb][aC1+1][aRow1] = f2tf32(fa1.y);
            As[nb][aC1+2][aRow1] = f2tf32(fa1.z); As[nb][aC1+3][aRow1] = f2tf32(fa1.w);
            Bs[nb][bK0][bN0+0] = f2tf32(fb0.x); Bs[nb][bK0][bN0+1] = f2tf32(fb0.y);
            Bs[nb][bK0][bN0+2] = f2tf32(fb0.z); Bs[nb][bK0][bN0+3] = f2tf32(fb0.w);
            Bs[nb][bK1][bN1+0] = f2tf32(fb1.x); Bs[nb][bK1][bN1+1] = f2tf32(fb1.y);
            Bs[nb][bK1][bN1+2] = f2tf32(fb1.z); Bs[nb][bK1][bN1+3] = f2tf32(fb1.w);
            __syncthreads();
            buf = nb;
        }
    }

    // epilogue: bias + store
#pragma unroll
    for (int mi = 0; mi < 4; mi++) {
        int r0 = rowBase + wm * 64 + mi * 16 + grp;
        int r1 = r0 + 8;
#pragma unroll
        for (int ni = 0; ni < 4; ni++) {
            int c = wn * 32 + ni * 8 + tig * 2;
            float b0 = bias[c], b1 = bias[c + 1];
            if (r0 < NN) {
                float2 o = make_float2(acc[mi][ni][0] + b0, acc[mi][ni][1] + b1);
                *reinterpret_cast<float2*>(C + (size_t)r0 * ldc + coloff + c) = o;
            }
            if (r1 < NN) {
                float2 o = make_float2(acc[mi][ni][2] + b0, acc[mi][ni][3] + b1);
                *reinterpret_cast<float2*>(C + (size_t)r1 * ldc + coloff + c) = o;
            }
        }
    }
}

// ---------------- fused attention: warp per dst node, online softmax, x2 unroll ----------------
__global__ __launch_bounds__(256) void attn_k(
    const int* __restrict__ ei, const float* __restrict__ ea,
    const float* __restrict__ We, const float* __restrict__ be,
    const float* __restrict__ qkv, float* __restrict__ agg)
{
    __shared__ float sWe[256];
    __shared__ float sbe[8];
    {
        int t = threadIdx.x;
        if (t < 256) sWe[t] = We[t];
        if (t < 8) sbe[t] = be[t];
    }
    __syncthreads();

    const int warp = threadIdx.x >> 5;
    const int lane = threadIdx.x & 31;
    const int node = blockIdx.x * 8 + warp;
    if (node >= NN) return;

    const int g = lane >> 2;
    const int j = lane & 3;

    const int beg = g_off[node];
    const int end = g_off[node + 1];

    float* op = &agg[(size_t)node * 128 + lane * 4];
    if (beg == end) {
        *reinterpret_cast<float4*>(op) = make_float4(0.f, 0.f, 0.f, 0.f);
        return;
    }

    float4 qv = *reinterpret_cast<const float4*>(&qkv[(size_t)node * 384 + lane * 4]);
    const float beh = sbe[g];
    const float* wr = &sWe[(j * 8) * 8 + g];

    float m = -__int_as_float(0x7F800000);
    float d = 0.f;
    float4 acc = make_float4(0.f, 0.f, 0.f, 0.f);

    int idx = beg;
    for (; idx + 1 < end; idx += 2) {
        int eA = g_list[idx];
        int eB = g_list[idx + 1];
        int sA = ei[eA];
        int sB = ei[eB];

        // issue all loads for both edges up front
        float4 kA = *reinterpret_cast<const float4*>(&qkv[(size_t)sA * 384 + 128 + lane * 4]);
        float4 kB = *reinterpret_cast<const float4*>(&qkv[(size_t)sB * 384 + 128 + lane * 4]);
        float4 vA = *reinterpret_cast<const float4*>(&qkv[(size_t)sA * 384 + 256 + lane * 4]);
        float4 vB = *reinterpret_cast<const float4*>(&qkv[(size_t)sB * 384 + 256 + lane * 4]);
        const float4* epA = reinterpret_cast<const float4*>(ea + (size_t)eA * 32 + j * 8);
        const float4* epB = reinterpret_cast<const float4*>(ea + (size_t)eB * 32 + j * 8);
        float4 eA0 = epA[0], eA1 = epA[1];
        float4 eB0 = epB[0], eB1 = epB[1];

        float dotA = qv.x * kA.x + qv.y * kA.y + qv.z * kA.z + qv.w * kA.w;
        float dotB = qv.x * kB.x + qv.y * kB.y + qv.z * kB.z + qv.w * kB.w;
        float partA = eA0.x * wr[0]  + eA0.y * wr[8]  + eA0.z * wr[16] + eA0.w * wr[24]
                    + eA1.x * wr[32] + eA1.y * wr[40] + eA1.z * wr[48] + eA1.w * wr[56];
        float partB = eB0.x * wr[0]  + eB0.y * wr[8]  + eB0.z * wr[16] + eB0.w * wr[24]
                    + eB1.x * wr[32] + eB1.y * wr[40] + eB1.z * wr[48] + eB1.w * wr[56];

        float tA = dotA * 0.25f + partA;
        float tB = dotB * 0.25f + partB;
        tA += __shfl_xor_sync(0xffffffffu, tA, 1);
        tB += __shfl_xor_sync(0xffffffffu, tB, 1);
        tA += __shfl_xor_sync(0xffffffffu, tA, 2);
        tB += __shfl_xor_sync(0xffffffffu, tB, 2);
        float scA = tA + beh;
        float scB = tB + beh;

        float mn = fmaxf(m, fmaxf(scA, scB));
        float scale = __expf(m - mn);
        float pA = __expf(scA - mn);
        float pB = __expf(scB - mn);
        d = d * scale + pA + pB;
        acc.x = acc.x * scale + pA * vA.x + pB * vB.x;
        acc.y = acc.y * scale + pA * vA.y + pB * vB.y;
        acc.z = acc.z * scale + pA * vA.z + pB * vB.z;
        acc.w = acc.w * scale + pA * vA.w + pB * vB.w;
        m = mn;
    }
    if (idx < end) {
        int e = g_list[idx];
        int src = ei[e];
        float4 kv = *reinterpret_cast<const float4*>(&qkv[(size_t)src * 384 + 128 + lane * 4]);
        float4 vv = *reinterpret_cast<const float4*>(&qkv[(size_t)src * 384 + 256 + lane * 4]);
        const float4* ep = reinterpret_cast<const float4*>(ea + (size_t)e * 32 + j * 8);
        float4 e0 = ep[0], e1 = ep[1];

        float dot = qv.x * kv.x + qv.y * kv.y + qv.z * kv.z + qv.w * kv.w;
        float part = e0.x * wr[0]  + e0.y * wr[8]  + e0.z * wr[16] + e0.w * wr[24]
                   + e1.x * wr[32] + e1.y * wr[40] + e1.z * wr[48] + e1.w * wr[56];
        float s = dot * 0.25f + part;
        s += __shfl_xor_sync(0xffffffffu, s, 1);
        s += __shfl_xor_sync(0xffffffffu, s, 2);
        s += beh;

        float mn = fmaxf(m, s);
        float scale = __expf(m - mn);
        float p = __expf(s - mn);
        d = d * scale + p;
        acc.x = acc.x * scale + p * vv.x;
        acc.y = acc.y * scale + p * vv.y;
        acc.z = acc.z * scale + p * vv.z;
        acc.w = acc.w * scale + p * vv.w;
        m = mn;
    }

    float inv = 1.0f / d;
    *reinterpret_cast<float4*>(op) =
        make_float4(acc.x * inv, acc.y * inv, acc.z * inv, acc.w * inv);
}

// ---------------- LayerNorm ----------------
__global__ __launch_bounds__(128) void ln_k(
    const float* __restrict__ in, const float* __restrict__ gamma,
    const float* __restrict__ beta, float* __restrict__ out)
{
    int node = blockIdx.x;
    int t = threadIdx.x;
    float v = in[node * 128 + t];

    float s = v;
#pragma unroll
    for (int o = 16; o > 0; o >>= 1) s += __shfl_xor_sync(0xffffffffu, s, o);
    __shared__ float sh[4], sh2[4];
    int w = t >> 5, l = t & 31;
    if (l == 0) sh[w] = s;
    __syncthreads();
    float mean = (sh[0] + sh[1] + sh[2] + sh[3]) * (1.0f / 128.0f);

    float dv = v - mean;
    float s2 = dv * dv;
#pragma unroll
    for (int o = 16; o > 0; o >>= 1) s2 += __shfl_xor_sync(0xffffffffu, s2, o);
    if (l == 0) sh2[w] = s2;
    __syncthreads();
    float var = (sh2[0] + sh2[1] + sh2[2] + sh2[3]) * (1.0f / 128.0f);

    out[node * 128 + t] = dv * rsqrtf(var + 1e-5f) * gamma[t] + beta[t];
}

// ---------------- launch ----------------
extern "C" void kernel_launch(void* const* d_in, const int* in_sizes, int n_in,
                              void* d_out, int out_size)
{
    const float* x     = (const float*)d_in[0];
    const float* ea    = (const float*)d_in[1];
    const float* Wq    = (const float*)d_in[2];
    const float* bq    = (const float*)d_in[3];
    const float* Wk    = (const float*)d_in[4];
    const float* bk    = (const float*)d_in[5];
    const float* Wv    = (const float*)d_in[6];
    const float* bv    = (const float*)d_in[7];
    const float* We    = (const float*)d_in[8];
    const float* be    = (const float*)d_in[9];
    const float* Wo    = (const float*)d_in[10];
    const float* bo    = (const float*)d_in[11];
    const float* gamma = (const float*)d_in[12];
    const float* beta  = (const float*)d_in[13];
    const int*   ei    = (const int*)d_in[14];
    float* out = (float*)d_out;

    float *qkv, *agg, *tmp;
    cudaGetSymbolAddress((void**)&qkv, g_qkv);
    cudaGetSymbolAddress((void**)&agg, g_agg);
    cudaGetSymbolAddress((void**)&tmp, g_tmp);

    const int nTiles = (NN + 127) / 128;

    zero_cnt_k<<<(NN + 255) / 256, 256>>>();
    hist_k<<<(EE + 255) / 256, 256>>>(ei);
    scan_k<<<1, 1024>>>();
    scatter_k<<<(EE + 255) / 256, 256>>>(ei);

    gemm_tf32<<<nTiles, 256>>>(x, Wq, bq, qkv, 384, 0);
    gemm_tf32<<<nTiles, 256>>>(x, Wk, bk, qkv, 384, 128);
    gemm_tf32<<<nTiles, 256>>>(x, Wv, bv, qkv, 384, 256);

    attn_k<<<(NN + 7) / 8, 256>>>(ei, ea, We, be, qkv, agg);

    gemm_tf32<<<nTiles, 256>>>(agg, Wo, bo, tmp, 128, 0);
    ln_k<<<NN, 128>>>(tmp, gamma, beta, out);
}